// round 11
// baseline (speedup 1.0000x reference)
#include <cuda_runtime.h>
#include <cuda_bf16.h>
#include <math.h>
#include <stdint.h>

#define BATCH 2
#define LSEQ  2048
#define VOCAB 32000
#define EDIM  512
#define HDIM  1024
#define MDIM  256
#define PDIM  4096
#define ROWS  (BATCH*LSEQ)   /* 4096 */
#define GRU_BLOCKS 128
#define QKDIM 512            /* q(256) | k(256) fused */

// ---------------- scratch (__device__ globals: allocation-free) ----------------
__device__ float g_xp[(size_t)ROWS*3*HDIM];
__device__ float g_states[(size_t)ROWS*HDIM];
__device__ float g_qk[(size_t)ROWS*QKDIM];
__device__ float g_gate[ROWS];
__device__ float g_plin[(size_t)ROWS*PDIM];
__device__ float g_h[BATCH*HDIM];
__device__ unsigned g_bar;
__device__ int   g_t2p[VOCAB];
__device__ int   g_slots[ROWS];
__device__ float g_bqk[QKDIM];

// bf16 copies for tensor-core GEMMs
__device__ __nv_bfloat16 g_x_bf[ROWS*EDIM];
__device__ __nv_bfloat16 g_emb_bf[(size_t)VOCAB*EDIM];
__device__ __nv_bfloat16 g_states_bf[(size_t)ROWS*HDIM];
__device__ __nv_bfloat16 g_head_bf[(size_t)ROWS*4*EDIM];
__device__ __nv_bfloat16 g_feat_bf[ROWS*EDIM];
__device__ __nv_bfloat16 g_wih_bf[3*HDIM*EDIM];
__device__ __nv_bfloat16 g_wfc_bf[4*EDIM*HDIM];
__device__ __nv_bfloat16 g_wproj_bf[EDIM*4*EDIM];
__device__ __nv_bfloat16 g_wqk_bf[QKDIM*HDIM];
__device__ __nv_bfloat16 g_wpart_bf[PDIM*EDIM];

// ---------------- init / convert kernels ----------------
__global__ void init_a_kernel() {
    int i = blockIdx.x*256 + threadIdx.x;
    if (i < VOCAB) g_t2p[i] = -1;
    if (i < BATCH*HDIM) g_h[i] = 0.f;
    if (i == 0) g_bar = 0u;
}
__global__ void init_b_kernel(const int* __restrict__ untied) {
    int i = blockIdx.x*256 + threadIdx.x;
    if (i < PDIM) g_t2p[untied[i]] = i;
}
__global__ void init_c_kernel(const int* __restrict__ ids) {
    int i = blockIdx.x*256 + threadIdx.x;
    if (i < ROWS) g_slots[i] = g_t2p[ids[i]];
}
__global__ void bqk_kernel(const float* __restrict__ bq, const float* __restrict__ bk) {
    int i = blockIdx.x*256 + threadIdx.x;
    if (i < 256) g_bqk[i] = bq[i];
    else if (i < 512) g_bqk[i] = bk[i - 256];
}
__global__ void f2bf_kernel(const float* __restrict__ s, __nv_bfloat16* __restrict__ d, int n4) {
    int i = blockIdx.x*256 + threadIdx.x;
    if (i < n4) {
        float4 v = reinterpret_cast<const float4*>(s)[i];
        __nv_bfloat162 lo = __floats2bfloat162_rn(v.x, v.y);
        __nv_bfloat162 hi = __floats2bfloat162_rn(v.z, v.w);
        uint2 o;
        o.x = *reinterpret_cast<unsigned int*>(&lo);
        o.y = *reinterpret_cast<unsigned int*>(&hi);
        reinterpret_cast<uint2*>(d)[i] = o;
    }
}
__global__ void gather_x_bf_kernel(const int* __restrict__ ids, const float* __restrict__ emb) {
    int r = blockIdx.x;
    int tok = ids[r];
    const float4* src = reinterpret_cast<const float4*>(emb + (size_t)tok*EDIM);
    uint2* dst = reinterpret_cast<uint2*>(g_x_bf + (size_t)r*EDIM);
    for (int i = threadIdx.x; i < EDIM/4; i += 128) {
        float4 v = src[i];
        __nv_bfloat162 lo = __floats2bfloat162_rn(v.x, v.y);
        __nv_bfloat162 hi = __floats2bfloat162_rn(v.z, v.w);
        uint2 o;
        o.x = *reinterpret_cast<unsigned int*>(&lo);
        o.y = *reinterpret_cast<unsigned int*>(&hi);
        dst[i] = o;
    }
}

// ================= mma.sync bf16 GEMM =================
// C[M,N] = A[M,K] * B[N,K]^T + bias.
// EPI: 0 bias; 1 square(relu(x+bias)); 2 bias + gather-add tp[row][t2p[col]] (untied fusion)
__device__ __forceinline__ unsigned smem_u32(const void* p) {
    return (unsigned)__cvta_generic_to_shared(p);
}
__device__ __forceinline__ void cp16(unsigned dst, const void* src) {
    asm volatile("cp.async.cg.shared.global [%0], [%1], 16;" :: "r"(dst), "l"(src) : "memory");
}
__device__ __forceinline__ void ldsm4(unsigned addr, unsigned &r0, unsigned &r1, unsigned &r2, unsigned &r3) {
    asm volatile("ldmatrix.sync.aligned.m8n8.x4.shared.b16 {%0,%1,%2,%3}, [%4];"
        : "=r"(r0), "=r"(r1), "=r"(r2), "=r"(r3) : "r"(addr));
}
__device__ __forceinline__ void mma16816(float* c, unsigned a0, unsigned a1, unsigned a2, unsigned a3,
                                         unsigned b0, unsigned b1) {
    asm volatile("mma.sync.aligned.m16n8k16.row.col.f32.bf16.bf16.f32 "
        "{%0,%1,%2,%3}, {%4,%5,%6,%7}, {%8,%9}, {%0,%1,%2,%3};"
        : "+f"(c[0]), "+f"(c[1]), "+f"(c[2]), "+f"(c[3])
        : "r"(a0), "r"(a1), "r"(a2), "r"(a3), "r"(b0), "r"(b1));
}

#define TCS_STAGE 32768
#define TCS_DYN   (2*TCS_STAGE + 1024)

template<int EPI, int OBF>
__global__ __launch_bounds__(256, 2)
void mgemm(const __nv_bfloat16* __restrict__ A, const __nv_bfloat16* __restrict__ B,
           const float* __restrict__ bias, float* __restrict__ C,
           __nv_bfloat16* __restrict__ Cb, int M, int N, int K,
           const float* __restrict__ tp, const int* __restrict__ t2p)
{
    extern __shared__ char smx[];
    const unsigned sdyn  = smem_u32(smx);
    const unsigned sbase = (sdyn + 1023u) & ~1023u;
    char* dynp = smx + (sbase - sdyn);

    const int tid = threadIdx.x, warp = tid >> 5, lane = tid & 31;
    const int wm = warp & 3, wn = warp >> 2;
    const int bm = blockIdx.y * 128, bn = blockIdx.x * 128;

    const __nv_bfloat16* Abase = A + (size_t)bm * K;
    const __nv_bfloat16* Bbase = B + (size_t)bn * K;

    float acc[2][8][4];
    #pragma unroll
    for (int i = 0; i < 2; i++)
        #pragma unroll
        for (int j = 0; j < 8; j++)
            #pragma unroll
            for (int e = 0; e < 4; e++) acc[i][j][e] = 0.f;

    const int r_local = ((lane >> 3) & 1) * 8 + (lane & 7);
    unsigned koff[4];
    {
        unsigned kh = ((unsigned)(lane >> 4)) << 4;
        unsigned xm = ((unsigned)(lane & 7)) << 4;
        #pragma unroll
        for (int ks = 0; ks < 4; ks++) koff[ks] = (((unsigned)ks << 5) | kh) ^ xm;
    }
    unsigned aoff[2], boff[4];
    #pragma unroll
    for (int im = 0; im < 2; im++) aoff[im] = (unsigned)((wm*32 + im*16 + r_local) * 128);
    #pragma unroll
    for (int jn = 0; jn < 4; jn++) boff[jn] = (unsigned)((wn*64 + jn*16 + r_local) * 128);

    auto load_stage = [&](int s, int k0) {
        unsigned a_s = sbase + (unsigned)s * TCS_STAGE;
        unsigned b_s = a_s + 16384u;
        #pragma unroll
        for (int j = 0; j < 4; j++) {
            int id = tid + (j << 8);
            int r = id >> 3, c16 = id & 7;
            unsigned so = (unsigned)(r * 128) + ((((unsigned)c16) << 4) ^ (((unsigned)(r & 7)) << 4));
            cp16(a_s + so, Abase + (size_t)r * K + k0 + c16 * 8);
            cp16(b_s + so, Bbase + (size_t)r * K + k0 + c16 * 8);
        }
        asm volatile("cp.async.commit_group;" ::: "memory");
    };

    const int NC = K >> 6;
    load_stage(0, 0);
    for (int c = 0; c < NC; c++) {
        const int s = c & 1;
        if (c + 1 < NC) {
            load_stage(s ^ 1, (c + 1) << 6);
            asm volatile("cp.async.wait_group 1;" ::: "memory");
        } else {
            asm volatile("cp.async.wait_group 0;" ::: "memory");
        }
        __syncthreads();
        const unsigned a_s = sbase + (unsigned)s * TCS_STAGE;
        const unsigned b_s = a_s + 16384u;
        #pragma unroll
        for (int ks = 0; ks < 4; ks++) {
            unsigned af[2][4];
            #pragma unroll
            for (int im = 0; im < 2; im++)
                ldsm4(a_s + aoff[im] + koff[ks], af[im][0], af[im][1], af[im][2], af[im][3]);
            #pragma unroll
            for (int jn = 0; jn < 4; jn++) {
                unsigned b0, b1, b2, b3;
                ldsm4(b_s + boff[jn] + koff[ks], b0, b1, b2, b3);
                #pragma unroll
                for (int im = 0; im < 2; im++) {
                    mma16816(acc[im][jn*2 + 0], af[im][0], af[im][1], af[im][2], af[im][3], b0, b2);
                    mma16816(acc[im][jn*2 + 1], af[im][0], af[im][1], af[im][2], af[im][3], b1, b3);
                }
            }
        }
        __syncthreads();
    }

    // epilogue: per-warp smem patch, coalesced stores
    float* patch = reinterpret_cast<float*>(dynp) + warp * (32 * 36);
    const int row0 = bm + wm * 32;
    const int colw = bn + wn * 64;
    #pragma unroll
    for (int hf = 0; hf < 2; hf++) {
        #pragma unroll
        for (int im = 0; im < 2; im++)
            #pragma unroll
            for (int t4 = 0; t4 < 4; t4++) {
                const int t = hf * 4 + t4;
                const int r = im * 16 + (lane >> 2);
                const int cl = t4 * 8 + (lane & 3) * 2;
                const int cg = colw + hf * 32 + cl;
                float bz0 = __ldg(&bias[cg]), bz1 = __ldg(&bias[cg + 1]);
                float v0 = acc[im][t][0] + bz0;
                float v1 = acc[im][t][1] + bz1;
                float v2 = acc[im][t][2] + bz0;
                float v3 = acc[im][t][3] + bz1;
                if (EPI == 1) {
                    v0 = v0 > 0.f ? v0 * v0 : 0.f;
                    v1 = v1 > 0.f ? v1 * v1 : 0.f;
                    v2 = v2 > 0.f ? v2 * v2 : 0.f;
                    v3 = v3 > 0.f ? v3 * v3 : 0.f;
                }
                if (EPI == 2) {
                    int p0 = __ldg(&t2p[cg]);
                    int p1 = __ldg(&t2p[cg + 1]);
                    int rg0 = row0 + r, rg1 = row0 + r + 8;
                    if (p0 >= 0) {
                        v0 += __ldg(&tp[(size_t)rg0 * PDIM + p0]);
                        v2 += __ldg(&tp[(size_t)rg1 * PDIM + p0]);
                    }
                    if (p1 >= 0) {
                        v1 += __ldg(&tp[(size_t)rg0 * PDIM + p1]);
                        v3 += __ldg(&tp[(size_t)rg1 * PDIM + p1]);
                    }
                }
                patch[r * 36 + cl]       = v0;
                patch[r * 36 + cl + 1]   = v1;
                patch[(r + 8) * 36 + cl]     = v2;
                patch[(r + 8) * 36 + cl + 1] = v3;
            }
        __syncwarp();
        #pragma unroll
        for (int it = 0; it < 8; it++) {
            int sIdx = lane + (it << 5);
            int rr = sIdx >> 3, q = sIdx & 7;
            float4 v = *reinterpret_cast<float4*>(&patch[rr * 36 + q * 4]);
            size_t g = (size_t)(row0 + rr) * N + colw + hf * 32 + q * 4;
            if (OBF) {
                __nv_bfloat162 lo = __floats2bfloat162_rn(v.x, v.y);
                __nv_bfloat162 hi = __floats2bfloat162_rn(v.z, v.w);
                uint2 o;
                o.x = *reinterpret_cast<unsigned int*>(&lo);
                o.y = *reinterpret_cast<unsigned int*>(&hi);
                *reinterpret_cast<uint2*>(&Cb[g]) = o;
            } else {
                *reinterpret_cast<float4*>(&C[g]) = v;
            }
        }
        __syncwarp();
    }
}

// ---------------- persistent GRU scan (atomic grid barrier — proven correct) ----------------
__global__ __launch_bounds__(256, 1) void gru_kernel(
    const float* __restrict__ xp, const float* __restrict__ w_hh,
    const float* __restrict__ b_hh, float* __restrict__ states)
{
    const int warp = threadIdx.x >> 5;
    const int lane = threadIdx.x & 31;
    const int j = blockIdx.x * 8 + warp;

    float Wr[32], Wz[32], Wn[32];
    #pragma unroll
    for (int i = 0; i < 32; i++) {
        int c = lane + 32*i;
        Wr[i] = w_hh[(size_t)j*HDIM + c];
        Wz[i] = w_hh[(size_t)(HDIM + j)*HDIM + c];
        Wn[i] = w_hh[(size_t)(2*HDIM + j)*HDIM + c];
    }
    const float bhr = b_hh[j], bhz = b_hh[HDIM + j], bhn = b_hh[2*HDIM + j];

    __shared__ float hs[BATCH][HDIM];

    for (int t = 0; t < LSEQ; t++) {
        for (int idx = threadIdx.x; idx < BATCH*HDIM; idx += 256)
            (&hs[0][0])[idx] = __ldcg(&g_h[idx]);
        __syncthreads();

        float ar0=0.f,az0=0.f,an0=0.f, ar1=0.f,az1=0.f,an1=0.f;
        #pragma unroll
        for (int i = 0; i < 32; i++) {
            int c = lane + 32*i;
            float h0 = hs[0][c], h1 = hs[1][c];
            ar0 += Wr[i]*h0; az0 += Wz[i]*h0; an0 += Wn[i]*h0;
            ar1 += Wr[i]*h1; az1 += Wz[i]*h1; an1 += Wn[i]*h1;
        }
        #pragma unroll
        for (int off = 16; off; off >>= 1) {
            ar0 += __shfl_xor_sync(0xffffffffu, ar0, off);
            az0 += __shfl_xor_sync(0xffffffffu, az0, off);
            an0 += __shfl_xor_sync(0xffffffffu, an0, off);
            ar1 += __shfl_xor_sync(0xffffffffu, ar1, off);
            az1 += __shfl_xor_sync(0xffffffffu, az1, off);
            an1 += __shfl_xor_sync(0xffffffffu, an1, off);
        }
        if (lane < BATCH) {
            float hr, hz, hn;
            if (lane == 0) { hr = ar0; hz = az0; hn = an0; }
            else           { hr = ar1; hz = az1; hn = an1; }
            hr += bhr; hz += bhz; hn += bhn;
            const float* xrow = xp + ((size_t)(lane*LSEQ + t))*(3*HDIM);
            float r = 1.f/(1.f + __expf(-(xrow[j]          + hr)));
            float z = 1.f/(1.f + __expf(-(xrow[HDIM + j]   + hz)));
            float n = tanhf(xrow[2*HDIM + j] + r*hn);
            float hprev = hs[lane][j];
            float hnew = (1.f - z)*n + z*hprev;
            g_h[lane*HDIM + j] = hnew;
            size_t sidx = ((size_t)(lane*LSEQ + t))*HDIM + j;
            states[sidx] = hnew;
            g_states_bf[sidx] = __float2bfloat16(hnew);
            __threadfence();
        }
        __syncthreads();
        if (threadIdx.x == 0) {
            atomicAdd(&g_bar, 1u);
            unsigned target = (unsigned)GRU_BLOCKS * (unsigned)(t + 1);
            while (*((volatile unsigned*)&g_bar) < target) { }
            __threadfence();
        }
        __syncthreads();
    }
}

// ---------------- gate ----------------
__global__ __launch_bounds__(256) void gate_kernel(
    const float* __restrict__ states, const float* __restrict__ wg,
    const float* __restrict__ bg, const float* __restrict__ ms)
{
    int r = blockIdx.x;
    float s = 0.f;
    for (int m = threadIdx.x; m < HDIM; m += 256)
        s += states[(size_t)r*HDIM + m] * wg[m];
    __shared__ float red[256];
    red[threadIdx.x] = s; __syncthreads();
    for (int o = 128; o; o >>= 1) { if (threadIdx.x < o) red[threadIdx.x] += red[threadIdx.x + o]; __syncthreads(); }
    if (threadIdx.x == 0) {
        float v = red[0] + bg[0];
        g_gate[r] = (1.f/(1.f + __expf(-v))) * ms[0];
    }
}

// ---------------- attention + softmax + scatter into g_plin (no out access) ----------------
__global__ __launch_bounds__(256) void attn_scatter_kernel()
{
    const int r = blockIdx.x;
    const int b = r >> 11, l = r & (LSEQ - 1);
    const int tid = threadIdx.x;
    __shared__ float q_s[MDIM];
    __shared__ float sc[LSEQ];
    __shared__ float accp[PDIM];
    __shared__ float red[256];

    for (int p = tid; p < PDIM; p += 256) accp[p] = 0.f;

    if (l > 0) {
        for (int m = tid; m < MDIM; m += 256) q_s[m] = g_qk[(size_t)r*QKDIM + m];
        __syncthreads();
        const float* kb = g_qk + (size_t)b*LSEQ*QKDIM + MDIM;
        for (int jj = tid; jj < l; jj += 256) {
            const float4* kr = reinterpret_cast<const float4*>(kb + (size_t)jj*QKDIM);
            const float4* qr = reinterpret_cast<const float4*>(q_s);
            float s = 0.f;
            #pragma unroll 8
            for (int m = 0; m < MDIM/4; m++) {
                float4 kv = kr[m], qv = qr[m];
                s += kv.x*qv.x + kv.y*qv.y + kv.z*qv.z + kv.w*qv.w;
            }
            sc[jj] = s * 0.0625f;
        }
        __syncthreads();
        float mx = -3.4e38f;
        for (int jj = tid; jj < l; jj += 256) mx = fmaxf(mx, sc[jj]);
        red[tid] = mx; __syncthreads();
        for (int o = 128; o; o >>= 1) { if (tid < o) red[tid] = fmaxf(red[tid], red[tid + o]); __syncthreads(); }
        mx = red[0]; __syncthreads();
        float ls = 0.f;
        for (int jj = tid; jj < l; jj += 256) { float e = __expf(sc[jj] - mx); sc[jj] = e; ls += e; }
        red[tid] = ls; __syncthreads();
        for (int o = 128; o; o >>= 1) { if (tid < o) red[tid] += red[tid + o]; __syncthreads(); }
        float coef = g_gate[r] / red[0];
        const int* sl = g_slots + b*LSEQ;
        for (int jj = tid; jj < l; jj += 256) {
            int s = sl[jj];
            if (s >= 0) atomicAdd(&accp[s], sc[jj]*coef);
        }
    }
    __syncthreads();
    float* pl = g_plin + (size_t)r*PDIM;
    for (int p = tid; p < PDIM; p += 256)
        pl[p] += accp[p];
}

// ---------------- launch ----------------
extern "C" void kernel_launch(void* const* d_in, const int* in_sizes, int n_in,
                              void* d_out, int out_size)
{
    const int*   ids     = (const int*)  d_in[0];
    const int*   untied  = (const int*)  d_in[1];
    const float* emb     = (const float*)d_in[2];
    const float* w_ih    = (const float*)d_in[3];
    const float* w_hh    = (const float*)d_in[4];
    const float* b_ih    = (const float*)d_in[5];
    const float* b_hh    = (const float*)d_in[6];
    const float* wq      = (const float*)d_in[7];
    const float* bq      = (const float*)d_in[8];
    const float* wk      = (const float*)d_in[9];
    const float* bk      = (const float*)d_in[10];
    const float* wg      = (const float*)d_in[11];
    const float* bg      = (const float*)d_in[12];
    const float* w_fc    = (const float*)d_in[13];
    const float* b_fc    = (const float*)d_in[14];
    const float* w_proj  = (const float*)d_in[15];
    const float* b_proj  = (const float*)d_in[16];
    const float* obias   = (const float*)d_in[17];
    const float* w_part  = (const float*)d_in[18];
    const float* b_part  = (const float*)d_in[19];
    const float* mscale  = (const float*)d_in[20];
    float* out = (float*)d_out;

    float *pxp, *pstates, *pqk, *pplin, *pbqk;
    int *pt2p;
    __nv_bfloat16 *px_bf, *pemb_bf, *pst_bf, *phead_bf, *pfeat_bf;
    __nv_bfloat16 *pwih, *pwfc, *pwproj, *pwqk, *pwpart;
    cudaGetSymbolAddress((void**)&pxp,     g_xp);
    cudaGetSymbolAddress((void**)&pstates, g_states);
    cudaGetSymbolAddress((void**)&pqk,     g_qk);
    cudaGetSymbolAddress((void**)&pplin,   g_plin);
    cudaGetSymbolAddress((void**)&pbqk,    g_bqk);
    cudaGetSymbolAddress((void**)&pt2p,    g_t2p);
    cudaGetSymbolAddress((void**)&px_bf,   g_x_bf);
    cudaGetSymbolAddress((void**)&pemb_bf, g_emb_bf);
    cudaGetSymbolAddress((void**)&pst_bf,  g_states_bf);
    cudaGetSymbolAddress((void**)&phead_bf,g_head_bf);
    cudaGetSymbolAddress((void**)&pfeat_bf,g_feat_bf);
    cudaGetSymbolAddress((void**)&pwih,    g_wih_bf);
    cudaGetSymbolAddress((void**)&pwfc,    g_wfc_bf);
    cudaGetSymbolAddress((void**)&pwproj,  g_wproj_bf);
    cudaGetSymbolAddress((void**)&pwqk,    g_wqk_bf);
    cudaGetSymbolAddress((void**)&pwpart,  g_wpart_bf);

    cudaFuncSetAttribute(mgemm<0,0>, cudaFuncAttributeMaxDynamicSharedMemorySize, TCS_DYN);
    cudaFuncSetAttribute(mgemm<1,1>, cudaFuncAttributeMaxDynamicSharedMemorySize, TCS_DYN);
    cudaFuncSetAttribute(mgemm<0,1>, cudaFuncAttributeMaxDynamicSharedMemorySize, TCS_DYN);
    cudaFuncSetAttribute(mgemm<2,0>, cudaFuncAttributeMaxDynamicSharedMemorySize, TCS_DYN);

    init_a_kernel<<<(VOCAB + 255)/256, 256>>>();
    init_b_kernel<<<(PDIM + 255)/256, 256>>>(untied);
    init_c_kernel<<<(ROWS + 255)/256, 256>>>(ids);
    bqk_kernel<<<2, 256>>>(bq, bk);

    auto conv = [](const float* s, __nv_bfloat16* d, size_t n) {
        int n4 = (int)(n >> 2);
        f2bf_kernel<<<(n4 + 255)/256, 256>>>(s, d, n4);
    };
    conv(emb,    pemb_bf, (size_t)VOCAB*EDIM);
    conv(w_ih,   pwih,    (size_t)3*HDIM*EDIM);
    conv(w_fc,   pwfc,    (size_t)4*EDIM*HDIM);
    conv(w_proj, pwproj,  (size_t)EDIM*4*EDIM);
    conv(wq,     pwqk,             (size_t)MDIM*HDIM);
    conv(wk,     pwqk + MDIM*HDIM, (size_t)MDIM*HDIM);
    conv(w_part, pwpart,  (size_t)PDIM*EDIM);
    gather_x_bf_kernel<<<ROWS, 128>>>(ids, emb);

    // xp = x @ w_ih^T + b_ih (fp32 out)   [4096, 3072]
    mgemm<0,0><<<dim3(3*HDIM/128, ROWS/128), 256, TCS_DYN>>>(px_bf, pwih, b_ih, pxp, nullptr, ROWS, 3*HDIM, EDIM, nullptr, nullptr);

    // sequential GRU scan -> states fp32 + bf16
    gru_kernel<<<GRU_BLOCKS, 256>>>(pxp, w_hh, b_hh, pstates);

    // head = relu(states @ w_fc^T + b_fc)^2 (bf16 out) [4096, 2048]
    mgemm<1,1><<<dim3(4*EDIM/128, ROWS/128), 256, TCS_DYN>>>(pst_bf, pwfc, b_fc, nullptr, phead_bf, ROWS, 4*EDIM, HDIM, nullptr, nullptr);
    // base_feat = head @ w_proj^T + b_proj (bf16 out)  [4096, 512]
    mgemm<0,1><<<dim3(EDIM/128, ROWS/128), 256, TCS_DYN>>>(phead_bf, pwproj, b_proj, nullptr, pfeat_bf, ROWS, EDIM, 4*EDIM, nullptr, nullptr);
    // qk fused (fp32 out)                               [4096, 512]
    mgemm<0,0><<<dim3(QKDIM/128, ROWS/128), 256, TCS_DYN>>>(pst_bf, pwqk, pbqk, pqk, nullptr, ROWS, QKDIM, HDIM, nullptr, nullptr);
    gate_kernel<<<ROWS, 256>>>(pstates, wg, bg, mscale);

    // part_lin = base_feat @ w_partial^T + b_partial [4096, 4096]
    mgemm<0,0><<<dim3(PDIM/128, ROWS/128), 256, TCS_DYN>>>(pfeat_bf, pwpart, b_part, pplin, nullptr, ROWS, PDIM, EDIM, nullptr, nullptr);

    // attention softmax + gated scatter folded into g_plin
    attn_scatter_kernel<<<ROWS, 256>>>();

    // base_logits + fused untied add -> d_out [4096, 32000]
    mgemm<2,0><<<dim3(VOCAB/128, ROWS/128), 256, TCS_DYN>>>(pfeat_bf, pemb_bf, obias, out, nullptr, ROWS, VOCAB, EDIM, pplin, pt2p);
}

// round 13
// speedup vs baseline: 1.0959x; 1.0959x over previous
#include <cuda_runtime.h>
#include <cuda_bf16.h>
#include <math.h>
#include <stdint.h>

#define BATCH 2
#define LSEQ  2048
#define VOCAB 32000
#define EDIM  512
#define HDIM  1024
#define MDIM  256
#define PDIM  4096
#define ROWS  (BATCH*LSEQ)   /* 4096 */
#define GRU_BLOCKS 128
#define QKDIM 512            /* q(256) | k(256) fused */

// ---------------- scratch (__device__ globals: allocation-free) ----------------
__device__ float g_xp[(size_t)ROWS*3*HDIM];
__device__ float g_qk[(size_t)ROWS*QKDIM];
__device__ float g_gate[ROWS];
__device__ float g_plin[(size_t)ROWS*PDIM];
__device__ float g_h[BATCH*HDIM];
__device__ unsigned g_bar;
__device__ int   g_t2p[VOCAB];
__device__ int   g_slots[ROWS];
__device__ float g_bqk[QKDIM];

// bf16 buffers for tensor-core GEMMs
__device__ __nv_bfloat16 g_x_bf[ROWS*EDIM];
__device__ __nv_bfloat16 g_emb_bf[(size_t)VOCAB*EDIM];
__device__ __nv_bfloat16 g_states_bf[(size_t)ROWS*HDIM];
__device__ __nv_bfloat16 g_head_bf[(size_t)ROWS*4*EDIM];
__device__ __nv_bfloat16 g_feat_bf[ROWS*EDIM];
__device__ __nv_bfloat16 g_wih_bf[3*HDIM*EDIM];
__device__ __nv_bfloat16 g_wfc_bf[4*EDIM*HDIM];
__device__ __nv_bfloat16 g_wproj_bf[EDIM*4*EDIM];
__device__ __nv_bfloat16 g_wqk_bf[QKDIM*HDIM];
__device__ __nv_bfloat16 g_wpart_bf[PDIM*EDIM];

// ---------------- init / convert kernels ----------------
__global__ void init_a_kernel() {
    int i = blockIdx.x*256 + threadIdx.x;
    if (i < VOCAB) g_t2p[i] = -1;
    if (i < BATCH*HDIM) g_h[i] = 0.f;
    if (i == 0) g_bar = 0u;
}
__global__ void init_b_kernel(const int* __restrict__ untied) {
    int i = blockIdx.x*256 + threadIdx.x;
    if (i < PDIM) g_t2p[untied[i]] = i;
}
__global__ void init_c_kernel(const int* __restrict__ ids) {
    int i = blockIdx.x*256 + threadIdx.x;
    if (i < ROWS) g_slots[i] = g_t2p[ids[i]];
}
__global__ void bqk_kernel(const float* __restrict__ bq, const float* __restrict__ bk) {
    int i = blockIdx.x*256 + threadIdx.x;
    if (i < 256) g_bqk[i] = bq[i];
    else if (i < 512) g_bqk[i] = bk[i - 256];
}
__global__ void f2bf_kernel(const float* __restrict__ s, __nv_bfloat16* __restrict__ d, int n4) {
    int i = blockIdx.x*256 + threadIdx.x;
    if (i < n4) {
        float4 v = reinterpret_cast<const float4*>(s)[i];
        __nv_bfloat162 lo = __floats2bfloat162_rn(v.x, v.y);
        __nv_bfloat162 hi = __floats2bfloat162_rn(v.z, v.w);
        uint2 o;
        o.x = *reinterpret_cast<unsigned int*>(&lo);
        o.y = *reinterpret_cast<unsigned int*>(&hi);
        reinterpret_cast<uint2*>(d)[i] = o;
    }
}
__global__ void gather_x_bf_kernel(const int* __restrict__ ids, const float* __restrict__ emb) {
    int r = blockIdx.x;
    int tok = ids[r];
    const float4* src = reinterpret_cast<const float4*>(emb + (size_t)tok*EDIM);
    uint2* dst = reinterpret_cast<uint2*>(g_x_bf + (size_t)r*EDIM);
    for (int i = threadIdx.x; i < EDIM/4; i += 128) {
        float4 v = src[i];
        __nv_bfloat162 lo = __floats2bfloat162_rn(v.x, v.y);
        __nv_bfloat162 hi = __floats2bfloat162_rn(v.z, v.w);
        uint2 o;
        o.x = *reinterpret_cast<unsigned int*>(&lo);
        o.y = *reinterpret_cast<unsigned int*>(&hi);
        dst[i] = o;
    }
}

// ================= mma.sync bf16 GEMM (3-stage cp.async pipeline) =================
// C[M,N] = A[M,K] * B[N,K]^T + bias.
// EPI: 0 bias; 1 square(relu(x+bias)); 2 bias + gather-add tp[row][t2p[col]]
__device__ __forceinline__ unsigned smem_u32(const void* p) {
    return (unsigned)__cvta_generic_to_shared(p);
}
__device__ __forceinline__ void cp16(unsigned dst, const void* src) {
    asm volatile("cp.async.cg.shared.global [%0], [%1], 16;" :: "r"(dst), "l"(src) : "memory");
}
__device__ __forceinline__ void ldsm4(unsigned addr, unsigned &r0, unsigned &r1, unsigned &r2, unsigned &r3) {
    asm volatile("ldmatrix.sync.aligned.m8n8.x4.shared.b16 {%0,%1,%2,%3}, [%4];"
        : "=r"(r0), "=r"(r1), "=r"(r2), "=r"(r3) : "r"(addr));
}
__device__ __forceinline__ void mma16816(float* c, unsigned a0, unsigned a1, unsigned a2, unsigned a3,
                                         unsigned b0, unsigned b1) {
    asm volatile("mma.sync.aligned.m16n8k16.row.col.f32.bf16.bf16.f32 "
        "{%0,%1,%2,%3}, {%4,%5,%6,%7}, {%8,%9}, {%0,%1,%2,%3};"
        : "+f"(c[0]), "+f"(c[1]), "+f"(c[2]), "+f"(c[3])
        : "r"(a0), "r"(a1), "r"(a2), "r"(a3), "r"(b0), "r"(b1));
}

#define TCS_STAGE 32768
#define TCS_STAGES 3
#define TCS_DYN   (TCS_STAGES*TCS_STAGE + 1024)

template<int EPI, int OBF>
__global__ __launch_bounds__(256, 2)
void mgemm(const __nv_bfloat16* __restrict__ A, const __nv_bfloat16* __restrict__ B,
           const float* __restrict__ bias, float* __restrict__ C,
           __nv_bfloat16* __restrict__ Cb, int M, int N, int K,
           const float* __restrict__ tp, const int* __restrict__ t2p)
{
    extern __shared__ char smx[];
    const unsigned sdyn  = smem_u32(smx);
    const unsigned sbase = (sdyn + 1023u) & ~1023u;
    char* dynp = smx + (sbase - sdyn);

    const int tid = threadIdx.x, warp = tid >> 5, lane = tid & 31;
    const int wm = warp & 3, wn = warp >> 2;
    const int bm = blockIdx.y * 128, bn = blockIdx.x * 128;

    const __nv_bfloat16* Abase = A + (size_t)bm * K;
    const __nv_bfloat16* Bbase = B + (size_t)bn * K;

    float acc[2][8][4];
    #pragma unroll
    for (int i = 0; i < 2; i++)
        #pragma unroll
        for (int j = 0; j < 8; j++)
            #pragma unroll
            for (int e = 0; e < 4; e++) acc[i][j][e] = 0.f;

    const int r_local = ((lane >> 3) & 1) * 8 + (lane & 7);
    unsigned koff[4];
    {
        unsigned kh = ((unsigned)(lane >> 4)) << 4;
        unsigned xm = ((unsigned)(lane & 7)) << 4;
        #pragma unroll
        for (int ks = 0; ks < 4; ks++) koff[ks] = (((unsigned)ks << 5) | kh) ^ xm;
    }
    unsigned aoff[2], boff[4];
    #pragma unroll
    for (int im = 0; im < 2; im++) aoff[im] = (unsigned)((wm*32 + im*16 + r_local) * 128);
    #pragma unroll
    for (int jn = 0; jn < 4; jn++) boff[jn] = (unsigned)((wn*64 + jn*16 + r_local) * 128);

    auto load_stage = [&](int s, int k0) {
        unsigned a_s = sbase + (unsigned)s * TCS_STAGE;
        unsigned b_s = a_s + 16384u;
        #pragma unroll
        for (int j = 0; j < 4; j++) {
            int id = tid + (j << 8);
            int r = id >> 3, c16 = id & 7;
            unsigned so = (unsigned)(r * 128) + ((((unsigned)c16) << 4) ^ (((unsigned)(r & 7)) << 4));
            cp16(a_s + so, Abase + (size_t)r * K + k0 + c16 * 8);
            cp16(b_s + so, Bbase + (size_t)r * K + k0 + c16 * 8);
        }
        asm volatile("cp.async.commit_group;" ::: "memory");
    };

    const int NC = K >> 6;
    load_stage(0, 0);
    load_stage(1, 64);
    for (int c = 0; c < NC; c++) {
        const int s = c % 3;
        if (c + 2 <= NC) { asm volatile("cp.async.wait_group 1;" ::: "memory"); }
        else             { asm volatile("cp.async.wait_group 0;" ::: "memory"); }
        __syncthreads();
        if (c + 2 < NC) load_stage((c + 2) % 3, (c + 2) << 6);
        const unsigned a_s = sbase + (unsigned)s * TCS_STAGE;
        const unsigned b_s = a_s + 16384u;
        #pragma unroll
        for (int ks = 0; ks < 4; ks++) {
            unsigned af[2][4];
            #pragma unroll
            for (int im = 0; im < 2; im++)
                ldsm4(a_s + aoff[im] + koff[ks], af[im][0], af[im][1], af[im][2], af[im][3]);
            #pragma unroll
            for (int jn = 0; jn < 4; jn++) {
                unsigned b0, b1, b2, b3;
                ldsm4(b_s + boff[jn] + koff[ks], b0, b1, b2, b3);
                #pragma unroll
                for (int im = 0; im < 2; im++) {
                    mma16816(acc[im][jn*2 + 0], af[im][0], af[im][1], af[im][2], af[im][3], b0, b2);
                    mma16816(acc[im][jn*2 + 1], af[im][0], af[im][1], af[im][2], af[im][3], b1, b3);
                }
            }
        }
    }
    __syncthreads();   // all compute done before patch reuses stage smem

    // epilogue: per-warp smem patch, coalesced stores
    float* patch = reinterpret_cast<float*>(dynp) + warp * (32 * 36);
    const int row0 = bm + wm * 32;
    const int colw = bn + wn * 64;
    #pragma unroll
    for (int hf = 0; hf < 2; hf++) {
        #pragma unroll
        for (int im = 0; im < 2; im++)
            #pragma unroll
            for (int t4 = 0; t4 < 4; t4++) {
                const int t = hf * 4 + t4;
                const int r = im * 16 + (lane >> 2);
                const int cl = t4 * 8 + (lane & 3) * 2;
                const int cg = colw + hf * 32 + cl;
                float bz0 = __ldg(&bias[cg]), bz1 = __ldg(&bias[cg + 1]);
                float v0 = acc[im][t][0] + bz0;
                float v1 = acc[im][t][1] + bz1;
                float v2 = acc[im][t][2] + bz0;
                float v3 = acc[im][t][3] + bz1;
                if (EPI == 1) {
                    v0 = v0 > 0.f ? v0 * v0 : 0.f;
                    v1 = v1 > 0.f ? v1 * v1 : 0.f;
                    v2 = v2 > 0.f ? v2 * v2 : 0.f;
                    v3 = v3 > 0.f ? v3 * v3 : 0.f;
                }
                if (EPI == 2) {
                    int p0 = __ldg(&t2p[cg]);
                    int p1 = __ldg(&t2p[cg + 1]);
                    int rg0 = row0 + r, rg1 = row0 + r + 8;
                    if (p0 >= 0) {
                        v0 += __ldg(&tp[(size_t)rg0 * PDIM + p0]);
                        v2 += __ldg(&tp[(size_t)rg1 * PDIM + p0]);
                    }
                    if (p1 >= 0) {
                        v1 += __ldg(&tp[(size_t)rg0 * PDIM + p1]);
                        v3 += __ldg(&tp[(size_t)rg1 * PDIM + p1]);
                    }
                }
                patch[r * 36 + cl]       = v0;
                patch[r * 36 + cl + 1]   = v1;
                patch[(r + 8) * 36 + cl]     = v2;
                patch[(r + 8) * 36 + cl + 1] = v3;
            }
        __syncwarp();
        #pragma unroll
        for (int it = 0; it < 8; it++) {
            int sIdx = lane + (it << 5);
            int rr = sIdx >> 3, q = sIdx & 7;
            float4 v = *reinterpret_cast<float4*>(&patch[rr * 36 + q * 4]);
            size_t g = (size_t)(row0 + rr) * N + colw + hf * 32 + q * 4;
            if (OBF) {
                __nv_bfloat162 lo = __floats2bfloat162_rn(v.x, v.y);
                __nv_bfloat162 hi = __floats2bfloat162_rn(v.z, v.w);
                uint2 o;
                o.x = *reinterpret_cast<unsigned int*>(&lo);
                o.y = *reinterpret_cast<unsigned int*>(&hi);
                *reinterpret_cast<uint2*>(&Cb[g]) = o;
            } else {
                *reinterpret_cast<float4*>(&C[g]) = v;
            }
        }
        __syncwarp();
    }
}

// ---------------- persistent GRU scan (atomic grid barrier; lean critical path) ----------------
__global__ __launch_bounds__(256, 1) void gru_kernel(
    const float* __restrict__ xp, const float* __restrict__ w_hh,
    const float* __restrict__ b_hh)
{
    const int warp = threadIdx.x >> 5;
    const int lane = threadIdx.x & 31;
    const int j = blockIdx.x * 8 + warp;

    float Wr[32], Wz[32], Wn[32];
    #pragma unroll
    for (int i = 0; i < 32; i++) {
        int c = lane + 32*i;
        Wr[i] = w_hh[(size_t)j*HDIM + c];
        Wz[i] = w_hh[(size_t)(HDIM + j)*HDIM + c];
        Wn[i] = w_hh[(size_t)(2*HDIM + j)*HDIM + c];
    }
    const float bhr = b_hh[j], bhz = b_hh[HDIM + j], bhn = b_hh[2*HDIM + j];

    __shared__ float hs[BATCH][HDIM];

    for (int t = 0; t < LSEQ; t++) {
        for (int idx = threadIdx.x; idx < BATCH*HDIM; idx += 256)
            (&hs[0][0])[idx] = __ldcg(&g_h[idx]);
        __syncthreads();

        float ar0=0.f,az0=0.f,an0=0.f, ar1=0.f,az1=0.f,an1=0.f;
        #pragma unroll
        for (int i = 0; i < 32; i++) {
            int c = lane + 32*i;
            float h0 = hs[0][c], h1 = hs[1][c];
            ar0 += Wr[i]*h0; az0 += Wz[i]*h0; an0 += Wn[i]*h0;
            ar1 += Wr[i]*h1; az1 += Wz[i]*h1; an1 += Wn[i]*h1;
        }
        #pragma unroll
        for (int off = 16; off; off >>= 1) {
            ar0 += __shfl_xor_sync(0xffffffffu, ar0, off);
            az0 += __shfl_xor_sync(0xffffffffu, az0, off);
            an0 += __shfl_xor_sync(0xffffffffu, an0, off);
            ar1 += __shfl_xor_sync(0xffffffffu, ar1, off);
            az1 += __shfl_xor_sync(0xffffffffu, az1, off);
            an1 += __shfl_xor_sync(0xffffffffu, an1, off);
        }
        float hnew = 0.f;
        if (lane < BATCH) {
            float hr, hz, hn;
            if (lane == 0) { hr = ar0; hz = az0; hn = an0; }
            else           { hr = ar1; hz = az1; hn = an1; }
            hr += bhr; hz += bhz; hn += bhn;
            const float* xrow = xp + ((size_t)(lane*LSEQ + t))*(3*HDIM);
            float r = 1.f/(1.f + __expf(-(xrow[j]          + hr)));
            float z = 1.f/(1.f + __expf(-(xrow[HDIM + j]   + hz)));
            float n = tanhf(xrow[2*HDIM + j] + r*hn);
            float hprev = hs[lane][j];
            hnew = (1.f - z)*n + z*hprev;
            g_h[lane*HDIM + j] = hnew;           // the ONLY store the fence must cover
            __threadfence();
        }
        __syncthreads();
        if (threadIdx.x == 0) {
            atomicAdd(&g_bar, 1u);
            unsigned target = (unsigned)GRU_BLOCKS * (unsigned)(t + 1);
            while (*((volatile unsigned*)&g_bar) < target) { }
            __threadfence();
        }
        __syncthreads();
        // states store off the critical path (value still in registers)
        if (lane < BATCH)
            g_states_bf[((size_t)(lane*LSEQ + t))*HDIM + j] = __float2bfloat16(hnew);
    }
}

// ---------------- gate (reads bf16 states) ----------------
__global__ __launch_bounds__(256) void gate_kernel(
    const __nv_bfloat16* __restrict__ st, const float* __restrict__ wg,
    const float* __restrict__ bg, const float* __restrict__ ms)
{
    int r = blockIdx.x;
    float s = 0.f;
    for (int m = threadIdx.x; m < HDIM; m += 256)
        s += __bfloat162float(st[(size_t)r*HDIM + m]) * wg[m];
    __shared__ float red[256];
    red[threadIdx.x] = s; __syncthreads();
    for (int o = 128; o; o >>= 1) { if (threadIdx.x < o) red[threadIdx.x] += red[threadIdx.x + o]; __syncthreads(); }
    if (threadIdx.x == 0) {
        float v = red[0] + bg[0];
        g_gate[r] = (1.f/(1.f + __expf(-v))) * ms[0];
    }
}

// ---------------- attention + softmax + scatter into g_plin ----------------
__global__ __launch_bounds__(256) void attn_scatter_kernel()
{
    const int r = blockIdx.x;
    const int b = r >> 11, l = r & (LSEQ - 1);
    const int tid = threadIdx.x;
    __shared__ float q_s[MDIM];
    __shared__ float sc[LSEQ];
    __shared__ float accp[PDIM];
    __shared__ float red[256];

    for (int p = tid; p < PDIM; p += 256) accp[p] = 0.f;

    if (l > 0) {
        for (int m = tid; m < MDIM; m += 256) q_s[m] = g_qk[(size_t)r*QKDIM + m];
        __syncthreads();
        const float* kb = g_qk + (size_t)b*LSEQ*QKDIM + MDIM;
        for (int jj = tid; jj < l; jj += 256) {
            const float4* kr = reinterpret_cast<const float4*>(kb + (size_t)jj*QKDIM);
            const float4* qr = reinterpret_cast<const float4*>(q_s);
            float s = 0.f;
            #pragma unroll 8
            for (int m = 0; m < MDIM/4; m++) {
                float4 kv = kr[m], qv = qr[m];
                s += kv.x*qv.x + kv.y*qv.y + kv.z*qv.z + kv.w*qv.w;
            }
            sc[jj] = s * 0.0625f;
        }
        __syncthreads();
        float mx = -3.4e38f;
        for (int jj = tid; jj < l; jj += 256) mx = fmaxf(mx, sc[jj]);
        red[tid] = mx; __syncthreads();
        for (int o = 128; o; o >>= 1) { if (tid < o) red[tid] = fmaxf(red[tid], red[tid + o]); __syncthreads(); }
        mx = red[0]; __syncthreads();
        float ls = 0.f;
        for (int jj = tid; jj < l; jj += 256) { float e = __expf(sc[jj] - mx); sc[jj] = e; ls += e; }
        red[tid] = ls; __syncthreads();
        for (int o = 128; o; o >>= 1) { if (tid < o) red[tid] += red[tid + o]; __syncthreads(); }
        float coef = g_gate[r] / red[0];
        const int* sl = g_slots + b*LSEQ;
        for (int jj = tid; jj < l; jj += 256) {
            int s = sl[jj];
            if (s >= 0) atomicAdd(&accp[s], sc[jj]*coef);
        }
    }
    __syncthreads();
    float* pl = g_plin + (size_t)r*PDIM;
    for (int p = tid; p < PDIM; p += 256)
        pl[p] += accp[p];
}

// ---------------- launch ----------------
extern "C" void kernel_launch(void* const* d_in, const int* in_sizes, int n_in,
                              void* d_out, int out_size)
{
    const int*   ids     = (const int*)  d_in[0];
    const int*   untied  = (const int*)  d_in[1];
    const float* emb     = (const float*)d_in[2];
    const float* w_ih    = (const float*)d_in[3];
    const float* w_hh    = (const float*)d_in[4];
    const float* b_ih    = (const float*)d_in[5];
    const float* b_hh    = (const float*)d_in[6];
    const float* wq      = (const float*)d_in[7];
    const float* bq      = (const float*)d_in[8];
    const float* wk      = (const float*)d_in[9];
    const float* bk      = (const float*)d_in[10];
    const float* wg      = (const float*)d_in[11];
    const float* bg      = (const float*)d_in[12];
    const float* w_fc    = (const float*)d_in[13];
    const float* b_fc    = (const float*)d_in[14];
    const float* w_proj  = (const float*)d_in[15];
    const float* b_proj  = (const float*)d_in[16];
    const float* obias   = (const float*)d_in[17];
    const float* w_part  = (const float*)d_in[18];
    const float* b_part  = (const float*)d_in[19];
    const float* mscale  = (const float*)d_in[20];
    float* out = (float*)d_out;

    float *pxp, *pqk, *pplin, *pbqk;
    int *pt2p;
    __nv_bfloat16 *px_bf, *pemb_bf, *pst_bf, *phead_bf, *pfeat_bf;
    __nv_bfloat16 *pwih, *pwfc, *pwproj, *pwqk, *pwpart;
    cudaGetSymbolAddress((void**)&pxp,     g_xp);
    cudaGetSymbolAddress((void**)&pqk,     g_qk);
    cudaGetSymbolAddress((void**)&pplin,   g_plin);
    cudaGetSymbolAddress((void**)&pbqk,    g_bqk);
    cudaGetSymbolAddress((void**)&pt2p,    g_t2p);
    cudaGetSymbolAddress((void**)&px_bf,   g_x_bf);
    cudaGetSymbolAddress((void**)&pemb_bf, g_emb_bf);
    cudaGetSymbolAddress((void**)&pst_bf,  g_states_bf);
    cudaGetSymbolAddress((void**)&phead_bf,g_head_bf);
    cudaGetSymbolAddress((void**)&pfeat_bf,g_feat_bf);
    cudaGetSymbolAddress((void**)&pwih,    g_wih_bf);
    cudaGetSymbolAddress((void**)&pwfc,    g_wfc_bf);
    cudaGetSymbolAddress((void**)&pwproj,  g_wproj_bf);
    cudaGetSymbolAddress((void**)&pwqk,    g_wqk_bf);
    cudaGetSymbolAddress((void**)&pwpart,  g_wpart_bf);

    cudaFuncSetAttribute(mgemm<0,0>, cudaFuncAttributeMaxDynamicSharedMemorySize, TCS_DYN);
    cudaFuncSetAttribute(mgemm<1,1>, cudaFuncAttributeMaxDynamicSharedMemorySize, TCS_DYN);
    cudaFuncSetAttribute(mgemm<0,1>, cudaFuncAttributeMaxDynamicSharedMemorySize, TCS_DYN);
    cudaFuncSetAttribute(mgemm<2,0>, cudaFuncAttributeMaxDynamicSharedMemorySize, TCS_DYN);

    init_a_kernel<<<(VOCAB + 255)/256, 256>>>();
    init_b_kernel<<<(PDIM + 255)/256, 256>>>(untied);
    init_c_kernel<<<(ROWS + 255)/256, 256>>>(ids);
    bqk_kernel<<<2, 256>>>(bq, bk);

    auto conv = [](const float* s, __nv_bfloat16* d, size_t n) {
        int n4 = (int)(n >> 2);
        f2bf_kernel<<<(n4 + 255)/256, 256>>>(s, d, n4);
    };
    conv(emb,    pemb_bf, (size_t)VOCAB*EDIM);
    conv(w_ih,   pwih,    (size_t)3*HDIM*EDIM);
    conv(w_fc,   pwfc,    (size_t)4*EDIM*HDIM);
    conv(w_proj, pwproj,  (size_t)EDIM*4*EDIM);
    conv(wq,     pwqk,             (size_t)MDIM*HDIM);
    conv(wk,     pwqk + MDIM*HDIM, (size_t)MDIM*HDIM);
    conv(w_part, pwpart,  (size_t)PDIM*EDIM);
    gather_x_bf_kernel<<<ROWS, 128>>>(ids, emb);

    // xp = x @ w_ih^T + b_ih (fp32 out)   [4096, 3072]
    mgemm<0,0><<<dim3(3*HDIM/128, ROWS/128), 256, TCS_DYN>>>(px_bf, pwih, b_ih, pxp, nullptr, ROWS, 3*HDIM, EDIM, nullptr, nullptr);

    // sequential GRU scan -> states bf16
    gru_kernel<<<GRU_BLOCKS, 256>>>(pxp, w_hh, b_hh);

    // head = relu(states @ w_fc^T + b_fc)^2 (bf16 out) [4096, 2048]
    mgemm<1,1><<<dim3(4*EDIM/128, ROWS/128), 256, TCS_DYN>>>(pst_bf, pwfc, b_fc, nullptr, phead_bf, ROWS, 4*EDIM, HDIM, nullptr, nullptr);
    // base_feat = head @ w_proj^T + b_proj (bf16 out)  [4096, 512]
    mgemm<0,1><<<dim3(EDIM/128, ROWS/128), 256, TCS_DYN>>>(phead_bf, pwproj, b_proj, nullptr, pfeat_bf, ROWS, EDIM, 4*EDIM, nullptr, nullptr);
    // qk fused (fp32 out)                               [4096, 512]
    mgemm<0,0><<<dim3(QKDIM/128, ROWS/128), 256, TCS_DYN>>>(pst_bf, pwqk, pbqk, pqk, nullptr, ROWS, QKDIM, HDIM, nullptr, nullptr);
    gate_kernel<<<ROWS, 256>>>(pst_bf, wg, bg, mscale);

    // part_lin = base_feat @ w_partial^T + b_partial [4096, 4096]
    mgemm<0,0><<<dim3(PDIM/128, ROWS/128), 256, TCS_DYN>>>(pfeat_bf, pwpart, b_part, pplin, nullptr, ROWS, PDIM, EDIM, nullptr, nullptr);

    // attention softmax + gated scatter folded into g_plin
    attn_scatter_kernel<<<ROWS, 256>>>();

    // base_logits + fused untied add -> d_out [4096, 32000]
    mgemm<2,0><<<dim3(VOCAB/128, ROWS/128), 256, TCS_DYN>>>(pfeat_bf, pemb_bf, obias, out, nullptr, ROWS, VOCAB, EDIM, pplin, pt2p);
}

// round 14
// speedup vs baseline: 1.4799x; 1.3504x over previous
#include <cuda_runtime.h>
#include <cuda_bf16.h>
#include <math.h>
#include <stdint.h>

#define BATCH 2
#define LSEQ  2048
#define VOCAB 32000
#define EDIM  512
#define HDIM  1024
#define MDIM  256
#define PDIM  4096
#define ROWS  (BATCH*LSEQ)   /* 4096 */
#define GRU_BLOCKS 128

// ---------------- scratch (__device__ globals: allocation-free) ----------------
__device__ float g_xp[(size_t)ROWS*3*HDIM];
__device__ float g_plin[(size_t)ROWS*PDIM];
__device__ float g_sc[(size_t)BATCH*LSEQ*LSEQ];   // attention scores S_b = Q_b K_b^T (33.5 MB)
__device__ float g_h[BATCH*HDIM];
__device__ unsigned g_bar;
__device__ int   g_t2p[VOCAB];
__device__ int   g_slots[ROWS];
__device__ float g_zero[LSEQ];

// bf16 buffers for tensor-core GEMMs
__device__ __nv_bfloat16 g_x_bf[ROWS*EDIM];
__device__ __nv_bfloat16 g_emb_bf[(size_t)VOCAB*EDIM];
__device__ __nv_bfloat16 g_states_bf[(size_t)ROWS*HDIM];
__device__ __nv_bfloat16 g_head_bf[(size_t)ROWS*4*EDIM];
__device__ __nv_bfloat16 g_feat_bf[ROWS*EDIM];
__device__ __nv_bfloat16 g_q_bf[ROWS*MDIM];
__device__ __nv_bfloat16 g_k_bf[ROWS*MDIM];
__device__ __nv_bfloat16 g_wih_bf[3*HDIM*EDIM];
__device__ __nv_bfloat16 g_wfc_bf[4*EDIM*HDIM];
__device__ __nv_bfloat16 g_wproj_bf[EDIM*4*EDIM];
__device__ __nv_bfloat16 g_wqk_bf[2*MDIM*HDIM];   // [wq | wk]
__device__ __nv_bfloat16 g_wpart_bf[PDIM*EDIM];

// ---------------- init / convert kernels ----------------
__global__ void init_a_kernel() {
    int i = blockIdx.x*256 + threadIdx.x;
    if (i < VOCAB) g_t2p[i] = -1;
    if (i < BATCH*HDIM) g_h[i] = 0.f;
    if (i < LSEQ) g_zero[i] = 0.f;
    if (i == 0) g_bar = 0u;
}
__global__ void init_b_kernel(const int* __restrict__ untied) {
    int i = blockIdx.x*256 + threadIdx.x;
    if (i < PDIM) g_t2p[untied[i]] = i;
}
__global__ void init_c_kernel(const int* __restrict__ ids) {
    int i = blockIdx.x*256 + threadIdx.x;
    if (i < ROWS) g_slots[i] = g_t2p[ids[i]];
}
__global__ void f2bf_kernel(const float* __restrict__ s, __nv_bfloat16* __restrict__ d, int n4) {
    int i = blockIdx.x*256 + threadIdx.x;
    if (i < n4) {
        float4 v = reinterpret_cast<const float4*>(s)[i];
        __nv_bfloat162 lo = __floats2bfloat162_rn(v.x, v.y);
        __nv_bfloat162 hi = __floats2bfloat162_rn(v.z, v.w);
        uint2 o;
        o.x = *reinterpret_cast<unsigned int*>(&lo);
        o.y = *reinterpret_cast<unsigned int*>(&hi);
        reinterpret_cast<uint2*>(d)[i] = o;
    }
}
__global__ void gather_x_bf_kernel(const int* __restrict__ ids, const float* __restrict__ emb) {
    int r = blockIdx.x;
    int tok = ids[r];
    const float4* src = reinterpret_cast<const float4*>(emb + (size_t)tok*EDIM);
    uint2* dst = reinterpret_cast<uint2*>(g_x_bf + (size_t)r*EDIM);
    for (int i = threadIdx.x; i < EDIM/4; i += 128) {
        float4 v = src[i];
        __nv_bfloat162 lo = __floats2bfloat162_rn(v.x, v.y);
        __nv_bfloat162 hi = __floats2bfloat162_rn(v.z, v.w);
        uint2 o;
        o.x = *reinterpret_cast<unsigned int*>(&lo);
        o.y = *reinterpret_cast<unsigned int*>(&hi);
        dst[i] = o;
    }
}

// ================= mma.sync bf16 GEMM (3-stage cp.async pipeline) =================
// C[M,N] = A[M,K] * B[N,K]^T + bias.
// EPI: 0 bias; 1 square(relu(x+bias)); 2 bias + gather-add tp[row][t2p[col]]
__device__ __forceinline__ unsigned smem_u32(const void* p) {
    return (unsigned)__cvta_generic_to_shared(p);
}
__device__ __forceinline__ void cp16(unsigned dst, const void* src) {
    asm volatile("cp.async.cg.shared.global [%0], [%1], 16;" :: "r"(dst), "l"(src) : "memory");
}
__device__ __forceinline__ void ldsm4(unsigned addr, unsigned &r0, unsigned &r1, unsigned &r2, unsigned &r3) {
    asm volatile("ldmatrix.sync.aligned.m8n8.x4.shared.b16 {%0,%1,%2,%3}, [%4];"
        : "=r"(r0), "=r"(r1), "=r"(r2), "=r"(r3) : "r"(addr));
}
__device__ __forceinline__ void mma16816(float* c, unsigned a0, unsigned a1, unsigned a2, unsigned a3,
                                         unsigned b0, unsigned b1) {
    asm volatile("mma.sync.aligned.m16n8k16.row.col.f32.bf16.bf16.f32 "
        "{%0,%1,%2,%3}, {%4,%5,%6,%7}, {%8,%9}, {%0,%1,%2,%3};"
        : "+f"(c[0]), "+f"(c[1]), "+f"(c[2]), "+f"(c[3])
        : "r"(a0), "r"(a1), "r"(a2), "r"(a3), "r"(b0), "r"(b1));
}

#define TCS_STAGE 32768
#define TCS_STAGES 3
#define TCS_DYN   (TCS_STAGES*TCS_STAGE + 1024)

template<int EPI, int OBF>
__global__ __launch_bounds__(256, 2)
void mgemm(const __nv_bfloat16* __restrict__ A, const __nv_bfloat16* __restrict__ B,
           const float* __restrict__ bias, float* __restrict__ C,
           __nv_bfloat16* __restrict__ Cb, int M, int N, int K,
           const float* __restrict__ tp, const int* __restrict__ t2p)
{
    extern __shared__ char smx[];
    const unsigned sdyn  = smem_u32(smx);
    const unsigned sbase = (sdyn + 1023u) & ~1023u;
    char* dynp = smx + (sbase - sdyn);

    const int tid = threadIdx.x, warp = tid >> 5, lane = tid & 31;
    const int wm = warp & 3, wn = warp >> 2;
    const int bm = blockIdx.y * 128, bn = blockIdx.x * 128;

    const __nv_bfloat16* Abase = A + (size_t)bm * K;
    const __nv_bfloat16* Bbase = B + (size_t)bn * K;

    float acc[2][8][4];
    #pragma unroll
    for (int i = 0; i < 2; i++)
        #pragma unroll
        for (int j = 0; j < 8; j++)
            #pragma unroll
            for (int e = 0; e < 4; e++) acc[i][j][e] = 0.f;

    const int r_local = ((lane >> 3) & 1) * 8 + (lane & 7);
    unsigned koff[4];
    {
        unsigned kh = ((unsigned)(lane >> 4)) << 4;
        unsigned xm = ((unsigned)(lane & 7)) << 4;
        #pragma unroll
        for (int ks = 0; ks < 4; ks++) koff[ks] = (((unsigned)ks << 5) | kh) ^ xm;
    }
    unsigned aoff[2], boff[4];
    #pragma unroll
    for (int im = 0; im < 2; im++) aoff[im] = (unsigned)((wm*32 + im*16 + r_local) * 128);
    #pragma unroll
    for (int jn = 0; jn < 4; jn++) boff[jn] = (unsigned)((wn*64 + jn*16 + r_local) * 128);

    auto load_stage = [&](int s, int k0) {
        unsigned a_s = sbase + (unsigned)s * TCS_STAGE;
        unsigned b_s = a_s + 16384u;
        #pragma unroll
        for (int j = 0; j < 4; j++) {
            int id = tid + (j << 8);
            int r = id >> 3, c16 = id & 7;
            unsigned so = (unsigned)(r * 128) + ((((unsigned)c16) << 4) ^ (((unsigned)(r & 7)) << 4));
            cp16(a_s + so, Abase + (size_t)r * K + k0 + c16 * 8);
            cp16(b_s + so, Bbase + (size_t)r * K + k0 + c16 * 8);
        }
        asm volatile("cp.async.commit_group;" ::: "memory");
    };

    const int NC = K >> 6;
    load_stage(0, 0);
    load_stage(1, 64);
    for (int c = 0; c < NC; c++) {
        const int s = c % 3;
        if (c + 2 <= NC) { asm volatile("cp.async.wait_group 1;" ::: "memory"); }
        else             { asm volatile("cp.async.wait_group 0;" ::: "memory"); }
        __syncthreads();
        if (c + 2 < NC) load_stage((c + 2) % 3, (c + 2) << 6);
        const unsigned a_s = sbase + (unsigned)s * TCS_STAGE;
        const unsigned b_s = a_s + 16384u;
        #pragma unroll
        for (int ks = 0; ks < 4; ks++) {
            unsigned af[2][4];
            #pragma unroll
            for (int im = 0; im < 2; im++)
                ldsm4(a_s + aoff[im] + koff[ks], af[im][0], af[im][1], af[im][2], af[im][3]);
            #pragma unroll
            for (int jn = 0; jn < 4; jn++) {
                unsigned b0, b1, b2, b3;
                ldsm4(b_s + boff[jn] + koff[ks], b0, b1, b2, b3);
                #pragma unroll
                for (int im = 0; im < 2; im++) {
                    mma16816(acc[im][jn*2 + 0], af[im][0], af[im][1], af[im][2], af[im][3], b0, b2);
                    mma16816(acc[im][jn*2 + 1], af[im][0], af[im][1], af[im][2], af[im][3], b1, b3);
                }
            }
        }
    }
    __syncthreads();

    // epilogue: per-warp smem patch, coalesced stores
    float* patch = reinterpret_cast<float*>(dynp) + warp * (32 * 36);
    const int row0 = bm + wm * 32;
    const int colw = bn + wn * 64;
    #pragma unroll
    for (int hf = 0; hf < 2; hf++) {
        #pragma unroll
        for (int im = 0; im < 2; im++)
            #pragma unroll
            for (int t4 = 0; t4 < 4; t4++) {
                const int t = hf * 4 + t4;
                const int r = im * 16 + (lane >> 2);
                const int cl = t4 * 8 + (lane & 3) * 2;
                const int cg = colw + hf * 32 + cl;
                float bz0 = __ldg(&bias[cg]), bz1 = __ldg(&bias[cg + 1]);
                float v0 = acc[im][t][0] + bz0;
                float v1 = acc[im][t][1] + bz1;
                float v2 = acc[im][t][2] + bz0;
                float v3 = acc[im][t][3] + bz1;
                if (EPI == 1) {
                    v0 = v0 > 0.f ? v0 * v0 : 0.f;
                    v1 = v1 > 0.f ? v1 * v1 : 0.f;
                    v2 = v2 > 0.f ? v2 * v2 : 0.f;
                    v3 = v3 > 0.f ? v3 * v3 : 0.f;
                }
                if (EPI == 2) {
                    int p0 = __ldg(&t2p[cg]);
                    int p1 = __ldg(&t2p[cg + 1]);
                    int rg0 = row0 + r, rg1 = row0 + r + 8;
                    if (p0 >= 0) {
                        v0 += __ldg(&tp[(size_t)rg0 * PDIM + p0]);
                        v2 += __ldg(&tp[(size_t)rg1 * PDIM + p0]);
                    }
                    if (p1 >= 0) {
                        v1 += __ldg(&tp[(size_t)rg0 * PDIM + p1]);
                        v3 += __ldg(&tp[(size_t)rg1 * PDIM + p1]);
                    }
                }
                patch[r * 36 + cl]       = v0;
                patch[r * 36 + cl + 1]   = v1;
                patch[(r + 8) * 36 + cl]     = v2;
                patch[(r + 8) * 36 + cl + 1] = v3;
            }
        __syncwarp();
        #pragma unroll
        for (int it = 0; it < 8; it++) {
            int sIdx = lane + (it << 5);
            int rr = sIdx >> 3, q = sIdx & 7;
            float4 v = *reinterpret_cast<float4*>(&patch[rr * 36 + q * 4]);
            size_t g = (size_t)(row0 + rr) * N + colw + hf * 32 + q * 4;
            if (OBF) {
                __nv_bfloat162 lo = __floats2bfloat162_rn(v.x, v.y);
                __nv_bfloat162 hi = __floats2bfloat162_rn(v.z, v.w);
                uint2 o;
                o.x = *reinterpret_cast<unsigned int*>(&lo);
                o.y = *reinterpret_cast<unsigned int*>(&hi);
                *reinterpret_cast<uint2*>(&Cb[g]) = o;
            } else {
                *reinterpret_cast<float4*>(&C[g]) = v;
            }
        }
        __syncwarp();
    }
}

// ---------------- persistent GRU scan (atomic barrier; xp prefetched off critical path) ----------------
__global__ __launch_bounds__(256, 1) void gru_kernel(
    const float* __restrict__ xp, const float* __restrict__ w_hh,
    const float* __restrict__ b_hh)
{
    const int warp = threadIdx.x >> 5;
    const int lane = threadIdx.x & 31;
    const int j = blockIdx.x * 8 + warp;

    float Wr[32], Wz[32], Wn[32];
    #pragma unroll
    for (int i = 0; i < 32; i++) {
        int c = lane + 32*i;
        Wr[i] = w_hh[(size_t)j*HDIM + c];
        Wz[i] = w_hh[(size_t)(HDIM + j)*HDIM + c];
        Wn[i] = w_hh[(size_t)(2*HDIM + j)*HDIM + c];
    }
    const float bhr = b_hh[j], bhz = b_hh[HDIM + j], bhn = b_hh[2*HDIM + j];

    __shared__ float hs[BATCH][HDIM];

    float xr = 0.f, xz = 0.f, xn = 0.f;
    if (lane < BATCH) {
        const float* xrow = xp + ((size_t)(lane*LSEQ))*(3*HDIM);
        xr = xrow[j]; xz = xrow[HDIM + j]; xn = xrow[2*HDIM + j];
    }

    for (int t = 0; t < LSEQ; t++) {
        for (int idx = threadIdx.x; idx < BATCH*HDIM; idx += 256)
            (&hs[0][0])[idx] = __ldcg(&g_h[idx]);
        __syncthreads();

        float ar0=0.f,az0=0.f,an0=0.f, ar1=0.f,az1=0.f,an1=0.f;
        #pragma unroll
        for (int i = 0; i < 32; i++) {
            int c = lane + 32*i;
            float h0 = hs[0][c], h1 = hs[1][c];
            ar0 += Wr[i]*h0; az0 += Wz[i]*h0; an0 += Wn[i]*h0;
            ar1 += Wr[i]*h1; az1 += Wz[i]*h1; an1 += Wn[i]*h1;
        }
        #pragma unroll
        for (int off = 16; off; off >>= 1) {
            ar0 += __shfl_xor_sync(0xffffffffu, ar0, off);
            az0 += __shfl_xor_sync(0xffffffffu, az0, off);
            an0 += __shfl_xor_sync(0xffffffffu, an0, off);
            ar1 += __shfl_xor_sync(0xffffffffu, ar1, off);
            az1 += __shfl_xor_sync(0xffffffffu, az1, off);
            an1 += __shfl_xor_sync(0xffffffffu, an1, off);
        }
        float hnew = 0.f;
        if (lane < BATCH) {
            float hr, hz, hn;
            if (lane == 0) { hr = ar0; hz = az0; hn = an0; }
            else           { hr = ar1; hz = az1; hn = an1; }
            hr += bhr; hz += bhz; hn += bhn;
            float r = 1.f/(1.f + __expf(-(xr + hr)));
            float z = 1.f/(1.f + __expf(-(xz + hz)));
            float n = tanhf(xn + r*hn);
            float hprev = hs[lane][j];
            hnew = (1.f - z)*n + z*hprev;
            g_h[lane*HDIM + j] = hnew;
            __threadfence();
            // prefetch next step's x (independent of h; lands during barrier wait)
            if (t + 1 < LSEQ) {
                const float* xrow = xp + ((size_t)(lane*LSEQ + t + 1))*(3*HDIM);
                xr = xrow[j]; xz = xrow[HDIM + j]; xn = xrow[2*HDIM + j];
            }
        }
        __syncthreads();
        if (threadIdx.x == 0) {
            atomicAdd(&g_bar, 1u);
            unsigned target = (unsigned)GRU_BLOCKS * (unsigned)(t + 1);
            while (*((volatile unsigned*)&g_bar) < target) { }
            __threadfence();
        }
        __syncthreads();
        if (lane < BATCH)
            g_states_bf[((size_t)(lane*LSEQ + t))*HDIM + j] = __float2bfloat16(hnew);
    }
}

// ---------------- softmax + gate + scatter into g_plin (scores precomputed by GEMM) ----------------
__global__ __launch_bounds__(256) void attn_scatter_kernel(
    const __nv_bfloat16* __restrict__ st, const float* __restrict__ wg,
    const float* __restrict__ bg, const float* __restrict__ ms)
{
    const int r = blockIdx.x;
    const int b = r >> 11, l = r & (LSEQ - 1);
    const int tid = threadIdx.x;
    __shared__ float sc[LSEQ];
    __shared__ float accp[PDIM];
    __shared__ float red[256];

    for (int p = tid; p < PDIM; p += 256) accp[p] = 0.f;

    if (l > 0) {
        // gate = sigmoid(st[r]·wg + bg) * ms
        float gs = 0.f;
        for (int m = tid; m < HDIM; m += 256)
            gs += __bfloat162float(st[(size_t)r*HDIM + m]) * wg[m];
        red[tid] = gs; __syncthreads();
        for (int o = 128; o; o >>= 1) { if (tid < o) red[tid] += red[tid + o]; __syncthreads(); }
        float gate = (1.f/(1.f + __expf(-(red[0] + bg[0])))) * ms[0];
        __syncthreads();

        // load precomputed scores (coalesced)
        const float* srow = g_sc + ((size_t)b*LSEQ + l)*LSEQ;
        float mx = -3.4e38f;
        for (int jj = tid; jj < l; jj += 256) {
            float s = srow[jj] * 0.0625f;
            sc[jj] = s;
            mx = fmaxf(mx, s);
        }
        red[tid] = mx; __syncthreads();
        for (int o = 128; o; o >>= 1) { if (tid < o) red[tid] = fmaxf(red[tid], red[tid + o]); __syncthreads(); }
        mx = red[0]; __syncthreads();
        float ls = 0.f;
        for (int jj = tid; jj < l; jj += 256) { float e = __expf(sc[jj] - mx); sc[jj] = e; ls += e; }
        red[tid] = ls; __syncthreads();
        for (int o = 128; o; o >>= 1) { if (tid < o) red[tid] += red[tid + o]; __syncthreads(); }
        float coef = gate / red[0];
        const int* sl = g_slots + b*LSEQ;
        for (int jj = tid; jj < l; jj += 256) {
            int s = sl[jj];
            if (s >= 0) atomicAdd(&accp[s], sc[jj]*coef);
        }
    }
    __syncthreads();
    float* pl = g_plin + (size_t)r*PDIM;
    for (int p = tid; p < PDIM; p += 256)
        pl[p] += accp[p];
}

// ---------------- launch ----------------
extern "C" void kernel_launch(void* const* d_in, const int* in_sizes, int n_in,
                              void* d_out, int out_size)
{
    const int*   ids     = (const int*)  d_in[0];
    const int*   untied  = (const int*)  d_in[1];
    const float* emb     = (const float*)d_in[2];
    const float* w_ih    = (const float*)d_in[3];
    const float* w_hh    = (const float*)d_in[4];
    const float* b_ih    = (const float*)d_in[5];
    const float* b_hh    = (const float*)d_in[6];
    const float* wq      = (const float*)d_in[7];
    const float* bq      = (const float*)d_in[8];
    const float* wk      = (const float*)d_in[9];
    const float* bk      = (const float*)d_in[10];
    const float* wg      = (const float*)d_in[11];
    const float* bg      = (const float*)d_in[12];
    const float* w_fc    = (const float*)d_in[13];
    const float* b_fc    = (const float*)d_in[14];
    const float* w_proj  = (const float*)d_in[15];
    const float* b_proj  = (const float*)d_in[16];
    const float* obias   = (const float*)d_in[17];
    const float* w_part  = (const float*)d_in[18];
    const float* b_part  = (const float*)d_in[19];
    const float* mscale  = (const float*)d_in[20];
    float* out = (float*)d_out;

    float *pxp, *pplin, *psc, *pzero;
    int *pt2p;
    __nv_bfloat16 *px_bf, *pemb_bf, *pst_bf, *phead_bf, *pfeat_bf, *pq_bf, *pk_bf;
    __nv_bfloat16 *pwih, *pwfc, *pwproj, *pwqk, *pwpart;
    cudaGetSymbolAddress((void**)&pxp,     g_xp);
    cudaGetSymbolAddress((void**)&pplin,   g_plin);
    cudaGetSymbolAddress((void**)&psc,     g_sc);
    cudaGetSymbolAddress((void**)&pzero,   g_zero);
    cudaGetSymbolAddress((void**)&pt2p,    g_t2p);
    cudaGetSymbolAddress((void**)&px_bf,   g_x_bf);
    cudaGetSymbolAddress((void**)&pemb_bf, g_emb_bf);
    cudaGetSymbolAddress((void**)&pst_bf,  g_states_bf);
    cudaGetSymbolAddress((void**)&phead_bf,g_head_bf);
    cudaGetSymbolAddress((void**)&pfeat_bf,g_feat_bf);
    cudaGetSymbolAddress((void**)&pq_bf,   g_q_bf);
    cudaGetSymbolAddress((void**)&pk_bf,   g_k_bf);
    cudaGetSymbolAddress((void**)&pwih,    g_wih_bf);
    cudaGetSymbolAddress((void**)&pwfc,    g_wfc_bf);
    cudaGetSymbolAddress((void**)&pwproj,  g_wproj_bf);
    cudaGetSymbolAddress((void**)&pwqk,    g_wqk_bf);
    cudaGetSymbolAddress((void**)&pwpart,  g_wpart_bf);

    cudaFuncSetAttribute(mgemm<0,0>, cudaFuncAttributeMaxDynamicSharedMemorySize, TCS_DYN);
    cudaFuncSetAttribute(mgemm<1,1>, cudaFuncAttributeMaxDynamicSharedMemorySize, TCS_DYN);
    cudaFuncSetAttribute(mgemm<0,1>, cudaFuncAttributeMaxDynamicSharedMemorySize, TCS_DYN);
    cudaFuncSetAttribute(mgemm<2,0>, cudaFuncAttributeMaxDynamicSharedMemorySize, TCS_DYN);

    init_a_kernel<<<(VOCAB + 255)/256, 256>>>();
    init_b_kernel<<<(PDIM + 255)/256, 256>>>(untied);
    init_c_kernel<<<(ROWS + 255)/256, 256>>>(ids);

    auto conv = [](const float* s, __nv_bfloat16* d, size_t n) {
        int n4 = (int)(n >> 2);
        f2bf_kernel<<<(n4 + 255)/256, 256>>>(s, d, n4);
    };
    conv(emb,    pemb_bf, (size_t)VOCAB*EDIM);
    conv(w_ih,   pwih,    (size_t)3*HDIM*EDIM);
    conv(w_fc,   pwfc,    (size_t)4*EDIM*HDIM);
    conv(w_proj, pwproj,  (size_t)EDIM*4*EDIM);
    conv(wq,     pwqk,             (size_t)MDIM*HDIM);
    conv(wk,     pwqk + MDIM*HDIM, (size_t)MDIM*HDIM);
    conv(w_part, pwpart,  (size_t)PDIM*EDIM);
    gather_x_bf_kernel<<<ROWS, 128>>>(ids, emb);

    // xp = x @ w_ih^T + b_ih (fp32 out)   [4096, 3072]
    mgemm<0,0><<<dim3(3*HDIM/128, ROWS/128), 256, TCS_DYN>>>(px_bf, pwih, b_ih, pxp, nullptr, ROWS, 3*HDIM, EDIM, nullptr, nullptr);

    // sequential GRU scan -> states bf16
    gru_kernel<<<GRU_BLOCKS, 256>>>(pxp, w_hh, b_hh);

    // head = relu(states @ w_fc^T + b_fc)^2 (bf16 out) [4096, 2048]
    mgemm<1,1><<<dim3(4*EDIM/128, ROWS/128), 256, TCS_DYN>>>(pst_bf, pwfc, b_fc, nullptr, phead_bf, ROWS, 4*EDIM, HDIM, nullptr, nullptr);
    // base_feat = head @ w_proj^T + b_proj (bf16 out)  [4096, 512]
    mgemm<0,1><<<dim3(EDIM/128, ROWS/128), 256, TCS_DYN>>>(phead_bf, pwproj, b_proj, nullptr, pfeat_bf, ROWS, EDIM, 4*EDIM, nullptr, nullptr);
    // q / k (bf16 out, contiguous)                      [4096, 256] each
    mgemm<0,1><<<dim3(MDIM/128, ROWS/128), 256, TCS_DYN>>>(pst_bf, pwqk, bq, nullptr, pq_bf, ROWS, MDIM, HDIM, nullptr, nullptr);
    mgemm<0,1><<<dim3(MDIM/128, ROWS/128), 256, TCS_DYN>>>(pst_bf, pwqk + MDIM*HDIM, bk, nullptr, pk_bf, ROWS, MDIM, HDIM, nullptr, nullptr);

    // attention scores S_b = Q_b @ K_b^T  [2048, 2048] per batch (tensor cores)
    for (int b = 0; b < BATCH; b++)
        mgemm<0,0><<<dim3(LSEQ/128, LSEQ/128), 256, TCS_DYN>>>(
            pq_bf + (size_t)b*LSEQ*MDIM, pk_bf + (size_t)b*LSEQ*MDIM,
            pzero, psc + (size_t)b*LSEQ*LSEQ, nullptr, LSEQ, LSEQ, MDIM, nullptr, nullptr);

    // part_lin = base_feat @ w_partial^T + b_partial [4096, 4096]
    mgemm<0,0><<<dim3(PDIM/128, ROWS/128), 256, TCS_DYN>>>(pfeat_bf, pwpart, b_part, pplin, nullptr, ROWS, PDIM, EDIM, nullptr, nullptr);

    // softmax + gate + gated scatter folded into g_plin
    attn_scatter_kernel<<<ROWS, 256>>>(pst_bf, wg, bg, mscale);

    // base_logits + fused untied add -> d_out [4096, 32000]
    mgemm<2,0><<<dim3(VOCAB/128, ROWS/128), 256, TCS_DYN>>>(pfeat_bf, pemb_bf, obias, out, nullptr, ROWS, VOCAB, EDIM, pplin, pt2p);
}